// round 2
// baseline (speedup 1.0000x reference)
#include <cuda_runtime.h>
#include <cuda_bf16.h>
#include <cstdint>

#define N_NODES 50000
#define N_EDGES 800000
#define D 128

// Scratch for support = X @ W  (25.6 MB). Device global: no allocation APIs.
__device__ float g_support[(size_t)N_NODES * D];

// ---------------------------------------------------------------------------
// Kernel 1: support = X @ W, fused with out = bias init for the same rows.
// Block tile: 128 rows x 128 cols (full W). Both tiles in smem, 8x8 per thread.
// ---------------------------------------------------------------------------
#define TILE_M 128
#define LDS_PAD 132   // 128 + 4 floats padding, keeps 16B alignment
#define GEMM_SMEM_BYTES (2 * TILE_M * LDS_PAD * 4)

__global__ __launch_bounds__(256, 1)
void gemm_kernel(const float* __restrict__ X,
                 const float* __restrict__ W,
                 const float* __restrict__ bias,
                 float* __restrict__ sup,
                 float* __restrict__ out) {
    extern __shared__ float smem[];
    float* Xs = smem;                      // [128][LDS_PAD]  Xs[r][k]
    float* Wt = smem + TILE_M * LDS_PAD;   // [128][LDS_PAD]  Wt[c][k] (transposed)

    const int tid  = threadIdx.x;
    const int row0 = blockIdx.x * TILE_M;

    // Load X tile (float4, coalesced). Out-of-range rows -> zeros.
    for (int idx = tid; idx < TILE_M * (D / 4); idx += 256) {
        int r  = idx >> 5;      // /32 float4s per row
        int c4 = idx & 31;
        float4 v = make_float4(0.f, 0.f, 0.f, 0.f);
        int gr = row0 + r;
        if (gr < N_NODES)
            v = *(const float4*)(X + (size_t)gr * D + c4 * 4);
        float* dst = Xs + r * LDS_PAD + c4 * 4;
        dst[0] = v.x; dst[1] = v.y; dst[2] = v.z; dst[3] = v.w;
    }

    // Load W transposed into Wt[c][k].
    for (int idx = tid; idx < D * (D / 4); idx += 256) {
        int k  = idx >> 5;
        int c4 = idx & 31;
        float4 v = *(const float4*)(W + k * D + c4 * 4);
        Wt[(c4 * 4 + 0) * LDS_PAD + k] = v.x;
        Wt[(c4 * 4 + 1) * LDS_PAD + k] = v.y;
        Wt[(c4 * 4 + 2) * LDS_PAD + k] = v.z;
        Wt[(c4 * 4 + 3) * LDS_PAD + k] = v.w;
    }
    __syncthreads();

    const int ty = tid >> 4;   // 0..15 -> rows ty + 16*i
    const int tx = tid & 15;   // 0..15 -> cols tx + 16*j

    float acc[8][8];
    #pragma unroll
    for (int i = 0; i < 8; i++)
        #pragma unroll
        for (int j = 0; j < 8; j++)
            acc[i][j] = 0.f;

    #pragma unroll 2
    for (int k = 0; k < D; k += 4) {
        float4 xa[8], wb[8];
        #pragma unroll
        for (int i = 0; i < 8; i++)
            xa[i] = *(const float4*)(Xs + (ty + 16 * i) * LDS_PAD + k);
        #pragma unroll
        for (int j = 0; j < 8; j++)
            wb[j] = *(const float4*)(Wt + (tx + 16 * j) * LDS_PAD + k);
        #pragma unroll
        for (int i = 0; i < 8; i++) {
            #pragma unroll
            for (int j = 0; j < 8; j++) {
                acc[i][j] += xa[i].x * wb[j].x;
                acc[i][j] += xa[i].y * wb[j].y;
                acc[i][j] += xa[i].z * wb[j].z;
                acc[i][j] += xa[i].w * wb[j].w;
            }
        }
    }

    // Bias values for this thread's 8 columns (broadcast loads, L1/const-hot).
    float bv[8];
    #pragma unroll
    for (int j = 0; j < 8; j++)
        bv[j] = __ldg(bias + tx + 16 * j);

    #pragma unroll
    for (int i = 0; i < 8; i++) {
        int gr = row0 + ty + 16 * i;
        if (gr < N_NODES) {
            #pragma unroll
            for (int j = 0; j < 8; j++) {
                sup[(size_t)gr * D + tx + 16 * j] = acc[i][j];
                out[(size_t)gr * D + tx + 16 * j] = bv[j];   // fused init
            }
        }
    }
}

// ---------------------------------------------------------------------------
// Kernel 2: scatter-add. One warp per 4 edges; lane l handles cols [4l, 4l+4).
// All 4 gathers issued before the REDs (MLP=4), then vector red.global.add.v4.
// ---------------------------------------------------------------------------
#define EDGES_PER_WARP 4

__global__ __launch_bounds__(256)
void scatter_kernel(const int* __restrict__ ei,
                    const float* __restrict__ ew,
                    const float* __restrict__ sup,
                    float* __restrict__ out) {
    const int gwarp = (blockIdx.x * 256 + threadIdx.x) >> 5;
    const int lane  = threadIdx.x & 31;
    const int e0    = gwarp * EDGES_PER_WARP;
    if (e0 >= N_EDGES) return;

    int   row[EDGES_PER_WARP], col[EDGES_PER_WARP];
    float w[EDGES_PER_WARP];
    bool  ok[EDGES_PER_WARP];

    #pragma unroll
    for (int i = 0; i < EDGES_PER_WARP; i++) {
        int e = e0 + i;
        ok[i] = (e < N_EDGES);
        int es = ok[i] ? e : (N_EDGES - 1);
        row[i] = __ldg(ei + es);            // destination
        col[i] = __ldg(ei + N_EDGES + es);  // source
        w[i]   = __ldg(ew + es);
    }

    float4 v[EDGES_PER_WARP];
    #pragma unroll
    for (int i = 0; i < EDGES_PER_WARP; i++)
        v[i] = *(const float4*)(sup + (size_t)col[i] * D + lane * 4);

    #pragma unroll
    for (int i = 0; i < EDGES_PER_WARP; i++) {
        if (ok[i]) {
            float* dst = out + (size_t)row[i] * D + lane * 4;
            asm volatile("red.global.add.v4.f32 [%0], {%1, %2, %3, %4};"
                         :: "l"(dst),
                            "f"(v[i].x * w[i]), "f"(v[i].y * w[i]),
                            "f"(v[i].z * w[i]), "f"(v[i].w * w[i])
                         : "memory");
        }
    }
}

// ---------------------------------------------------------------------------
extern "C" void kernel_launch(void* const* d_in, const int* in_sizes, int n_in,
                              void* d_out, int out_size) {
    const float* X    = (const float*)d_in[0];   // [N_NODES, D]
    const int*   ei   = (const int*)  d_in[1];   // [2, N_EDGES]
    const float* ew   = (const float*)d_in[2];   // [N_EDGES]
    const float* W    = (const float*)d_in[3];   // [D, D]
    const float* bias = (const float*)d_in[4];   // [D]
    float* out = (float*)d_out;

    float* sup;
    cudaGetSymbolAddress((void**)&sup, g_support);

    cudaFuncSetAttribute(gemm_kernel, cudaFuncAttributeMaxDynamicSharedMemorySize,
                         GEMM_SMEM_BYTES);

    // 1) support = X @ W  (+ fused out = bias for the same rows)
    {
        int grid = (N_NODES + TILE_M - 1) / TILE_M;  // 391
        gemm_kernel<<<grid, 256, GEMM_SMEM_BYTES>>>(X, W, bias, sup, out);
    }
    // 2) out[row] += support[col] * ew  (atomic scatter, 4 edges/warp)
    {
        int warps = (N_EDGES + EDGES_PER_WARP - 1) / EDGES_PER_WARP; // 200000
        int grid  = (warps + 7) / 8;                                  // 25000
        scatter_kernel<<<grid, 256>>>(ei, ew, sup, out);
    }
}

// round 3
// speedup vs baseline: 1.0998x; 1.0998x over previous
#include <cuda_runtime.h>
#include <cuda_bf16.h>
#include <cstdint>

#define N_NODES 50000
#define N_EDGES 800000
#define D 128

// Scratch (device globals: no allocation APIs allowed).
__device__ float g_support[(size_t)N_NODES * D];  // X @ W        (25.6 MB)
__device__ int   g_counts[N_NODES];               // per-row edge counts
__device__ int   g_offsets[N_NODES + 1];          // CSR row offsets
__device__ int   g_cursor[N_NODES];               // fill cursors
__device__ int2  g_edges[N_EDGES];                // (col, weight_bits) binned by row

// ---------------------------------------------------------------------------
// Kernel A: zero the per-row counters (must happen every call).
// ---------------------------------------------------------------------------
__global__ void zero_counts_kernel() {
    int i = blockIdx.x * blockDim.x + threadIdx.x;
    if (i < N_NODES) g_counts[i] = 0;
}

// ---------------------------------------------------------------------------
// Kernel B: histogram of destination rows.
// ---------------------------------------------------------------------------
__global__ void hist_kernel(const int* __restrict__ ei) {
    int e = blockIdx.x * blockDim.x + threadIdx.x;
    if (e < N_EDGES) atomicAdd(&g_counts[__ldg(ei + e)], 1);
}

// ---------------------------------------------------------------------------
// Kernel C: exclusive prefix scan of counts -> offsets (+ cursor copy).
// Single block of 1024 threads, 49 items each (1024*49 = 50176 >= 50000).
// ---------------------------------------------------------------------------
#define SCAN_ITEMS 49

__global__ __launch_bounds__(1024)
void scan_kernel() {
    __shared__ int tsum[1024];
    __shared__ int wsum[32];
    const int t = threadIdx.x;
    const int base = t * SCAN_ITEMS;

    int loc[SCAN_ITEMS];
    int s = 0;
    #pragma unroll
    for (int i = 0; i < SCAN_ITEMS; i++) {
        int idx = base + i;
        int c = (idx < N_NODES) ? g_counts[idx] : 0;
        loc[i] = s;            // exclusive within thread
        s += c;
    }
    tsum[t] = s;
    __syncthreads();

    const int lane = t & 31, wid = t >> 5;
    int v = tsum[t];
    int incl = v;
    #pragma unroll
    for (int d = 1; d < 32; d <<= 1) {
        int n = __shfl_up_sync(0xffffffffu, incl, d);
        if (lane >= d) incl += n;
    }
    if (lane == 31) wsum[wid] = incl;
    __syncthreads();
    if (wid == 0) {
        int wv = wsum[lane];
        int wi = wv;
        #pragma unroll
        for (int d = 1; d < 32; d <<= 1) {
            int n = __shfl_up_sync(0xffffffffu, wi, d);
            if (lane >= d) wi += n;
        }
        wsum[lane] = wi - wv;  // exclusive warp offset
    }
    __syncthreads();

    const int thread_excl = (incl - v) + wsum[wid];
    #pragma unroll
    for (int i = 0; i < SCAN_ITEMS; i++) {
        int idx = base + i;
        if (idx < N_NODES) {
            int off = thread_excl + loc[i];
            g_offsets[idx] = off;
            g_cursor[idx]  = off;
        }
    }
    if (t == 1023) g_offsets[N_NODES] = thread_excl + s;  // == N_EDGES
}

// ---------------------------------------------------------------------------
// Kernel D: fill CSR edge array with (col, weight_bits).
// ---------------------------------------------------------------------------
__global__ void fill_kernel(const int* __restrict__ ei,
                            const float* __restrict__ ew) {
    int e = blockIdx.x * blockDim.x + threadIdx.x;
    if (e >= N_EDGES) return;
    int   row = __ldg(ei + e);
    int   col = __ldg(ei + N_EDGES + e);
    float w   = __ldg(ew + e);
    int pos = atomicAdd(&g_cursor[row], 1);
    g_edges[pos] = make_int2(col, __float_as_int(w));
}

// ---------------------------------------------------------------------------
// Kernel E: support = X @ W  (128x128 block tile, 8x8 per thread).
// ---------------------------------------------------------------------------
#define TILE_M 128
#define LDS_PAD 132
#define GEMM_SMEM_BYTES (2 * TILE_M * LDS_PAD * 4)

__global__ __launch_bounds__(256, 1)
void gemm_kernel(const float* __restrict__ X,
                 const float* __restrict__ W,
                 float* __restrict__ sup) {
    extern __shared__ float smem[];
    float* Xs = smem;                      // [128][LDS_PAD]
    float* Wt = smem + TILE_M * LDS_PAD;   // [128][LDS_PAD] (transposed)

    const int tid  = threadIdx.x;
    const int row0 = blockIdx.x * TILE_M;

    for (int idx = tid; idx < TILE_M * (D / 4); idx += 256) {
        int r  = idx >> 5;
        int c4 = idx & 31;
        float4 v = make_float4(0.f, 0.f, 0.f, 0.f);
        int gr = row0 + r;
        if (gr < N_NODES)
            v = *(const float4*)(X + (size_t)gr * D + c4 * 4);
        float* dst = Xs + r * LDS_PAD + c4 * 4;
        dst[0] = v.x; dst[1] = v.y; dst[2] = v.z; dst[3] = v.w;
    }
    for (int idx = tid; idx < D * (D / 4); idx += 256) {
        int k  = idx >> 5;
        int c4 = idx & 31;
        float4 v = *(const float4*)(W + k * D + c4 * 4);
        Wt[(c4 * 4 + 0) * LDS_PAD + k] = v.x;
        Wt[(c4 * 4 + 1) * LDS_PAD + k] = v.y;
        Wt[(c4 * 4 + 2) * LDS_PAD + k] = v.z;
        Wt[(c4 * 4 + 3) * LDS_PAD + k] = v.w;
    }
    __syncthreads();

    const int ty = tid >> 4;
    const int tx = tid & 15;

    float acc[8][8];
    #pragma unroll
    for (int i = 0; i < 8; i++)
        #pragma unroll
        for (int j = 0; j < 8; j++)
            acc[i][j] = 0.f;

    #pragma unroll 2
    for (int k = 0; k < D; k += 4) {
        float4 xa[8], wb[8];
        #pragma unroll
        for (int i = 0; i < 8; i++)
            xa[i] = *(const float4*)(Xs + (ty + 16 * i) * LDS_PAD + k);
        #pragma unroll
        for (int j = 0; j < 8; j++)
            wb[j] = *(const float4*)(Wt + (tx + 16 * j) * LDS_PAD + k);
        #pragma unroll
        for (int i = 0; i < 8; i++) {
            #pragma unroll
            for (int j = 0; j < 8; j++) {
                acc[i][j] += xa[i].x * wb[j].x;
                acc[i][j] += xa[i].y * wb[j].y;
                acc[i][j] += xa[i].z * wb[j].z;
                acc[i][j] += xa[i].w * wb[j].w;
            }
        }
    }

    #pragma unroll
    for (int i = 0; i < 8; i++) {
        int gr = row0 + ty + 16 * i;
        if (gr < N_NODES) {
            #pragma unroll
            for (int j = 0; j < 8; j++)
                sup[(size_t)gr * D + tx + 16 * j] = acc[i][j];
        }
    }
}

// ---------------------------------------------------------------------------
// Kernel F: gather-aggregate. One warp per output row; lane l owns cols
// [4l, 4l+4). Accumulate all of the row's edges in registers, write once.
// No atomics anywhere.
// ---------------------------------------------------------------------------
__global__ __launch_bounds__(256)
void gather_kernel(const float* __restrict__ sup,
                   const float* __restrict__ bias,
                   float* __restrict__ out) {
    const int row  = (blockIdx.x * 256 + threadIdx.x) >> 5;
    const int lane = threadIdx.x & 31;
    if (row >= N_NODES) return;

    const int beg = __ldg(&g_offsets[row]);
    const int end = __ldg(&g_offsets[row + 1]);

    float4 acc = make_float4(0.f, 0.f, 0.f, 0.f);

    int e = beg;
    // Unroll-by-4: 4 independent gathers in flight (MLP).
    for (; e + 4 <= end; e += 4) {
        int2 m0 = g_edges[e + 0];
        int2 m1 = g_edges[e + 1];
        int2 m2 = g_edges[e + 2];
        int2 m3 = g_edges[e + 3];
        float4 v0 = *(const float4*)(sup + (size_t)m0.x * D + lane * 4);
        float4 v1 = *(const float4*)(sup + (size_t)m1.x * D + lane * 4);
        float4 v2 = *(const float4*)(sup + (size_t)m2.x * D + lane * 4);
        float4 v3 = *(const float4*)(sup + (size_t)m3.x * D + lane * 4);
        float w0 = __int_as_float(m0.y), w1 = __int_as_float(m1.y);
        float w2 = __int_as_float(m2.y), w3 = __int_as_float(m3.y);
        acc.x += v0.x * w0; acc.y += v0.y * w0; acc.z += v0.z * w0; acc.w += v0.w * w0;
        acc.x += v1.x * w1; acc.y += v1.y * w1; acc.z += v1.z * w1; acc.w += v1.w * w1;
        acc.x += v2.x * w2; acc.y += v2.y * w2; acc.z += v2.z * w2; acc.w += v2.w * w2;
        acc.x += v3.x * w3; acc.y += v3.y * w3; acc.z += v3.z * w3; acc.w += v3.w * w3;
    }
    for (; e < end; e++) {
        int2 m = g_edges[e];
        float4 v = *(const float4*)(sup + (size_t)m.x * D + lane * 4);
        float w = __int_as_float(m.y);
        acc.x += v.x * w; acc.y += v.y * w; acc.z += v.z * w; acc.w += v.w * w;
    }

    float4 b = *(const float4*)(bias + lane * 4);
    acc.x += b.x; acc.y += b.y; acc.z += b.z; acc.w += b.w;
    *(float4*)(out + (size_t)row * D + lane * 4) = acc;
}

// ---------------------------------------------------------------------------
extern "C" void kernel_launch(void* const* d_in, const int* in_sizes, int n_in,
                              void* d_out, int out_size) {
    const float* X    = (const float*)d_in[0];   // [N_NODES, D]
    const int*   ei   = (const int*)  d_in[1];   // [2, N_EDGES]
    const float* ew   = (const float*)d_in[2];   // [N_EDGES]
    const float* W    = (const float*)d_in[3];   // [D, D]
    const float* bias = (const float*)d_in[4];   // [D]
    float* out = (float*)d_out;

    float* sup;
    cudaGetSymbolAddress((void**)&sup, g_support);

    cudaFuncSetAttribute(gemm_kernel, cudaFuncAttributeMaxDynamicSharedMemorySize,
                         GEMM_SMEM_BYTES);

    // CSR build
    zero_counts_kernel<<<(N_NODES + 255) / 256, 256>>>();
    hist_kernel<<<(N_EDGES + 255) / 256, 256>>>(ei);
    scan_kernel<<<1, 1024>>>();
    fill_kernel<<<(N_EDGES + 255) / 256, 256>>>(ei, ew);

    // support = X @ W
    gemm_kernel<<<(N_NODES + TILE_M - 1) / TILE_M, 256, GEMM_SMEM_BYTES>>>(X, W, sup);

    // out[row] = sum_e sup[col_e] * w_e + bias   (one warp per row, no atomics)
    {
        int warps = N_NODES;
        int grid  = (warps * 32 + 255) / 256;  // 6250
        gather_kernel<<<grid, 256>>>(sup, bias, out);
    }
}

// round 4
// speedup vs baseline: 1.6832x; 1.5305x over previous
#include <cuda_runtime.h>
#include <cuda_bf16.h>
#include <cstdint>

#define N_NODES 50000
#define N_EDGES 800000
#define D 128
#define ROWS_PAD 50176            // 196 * 256, scan-friendly padding
#define ROWS_PER_BLK 32
#define CHUNK 1024

// Scratch (device globals: no allocation APIs allowed).
__device__ float g_support[(size_t)N_NODES * D];  // X @ W (25.6 MB)
__device__ int   g_counts[ROWS_PAD];
__device__ int   g_offsets[ROWS_PAD];
__device__ int   g_cursor[ROWS_PAD];
__device__ int2  g_edges[N_EDGES];                // (col, weight_bits), CSR-binned
__device__ int   g_base;                          // segment allocator

// ---------------------------------------------------------------------------
// A: zero counters + allocator.
// ---------------------------------------------------------------------------
__global__ void zero_kernel() {
    int i = blockIdx.x * blockDim.x + threadIdx.x;
    if (i < ROWS_PAD) g_counts[i] = 0;
    if (i == 0) g_base = 0;
}

// ---------------------------------------------------------------------------
// B: histogram of destination rows (4 edges/thread, vectorized).
// ---------------------------------------------------------------------------
__global__ void hist_kernel(const int* __restrict__ ei) {
    int i = blockIdx.x * blockDim.x + threadIdx.x;   // over N_EDGES/4
    if (i < N_EDGES / 4) {
        int4 r = ((const int4*)ei)[i];
        atomicAdd(&g_counts[r.x], 1);
        atomicAdd(&g_counts[r.y], 1);
        atomicAdd(&g_counts[r.z], 1);
        atomicAdd(&g_counts[r.w], 1);
    }
}

// ---------------------------------------------------------------------------
// C: block-parallel exclusive scan. Each 256-row block scans locally and
// grabs its base from a global allocator. Rows within a 256-block get
// contiguous, increasing segments (all the gather kernel needs).
// ---------------------------------------------------------------------------
__global__ __launch_bounds__(256)
void scan_kernel() {
    __shared__ int wsum[8];
    __shared__ int sbase;
    const int t = threadIdx.x;
    const int r = blockIdx.x * 256 + t;
    const int lane = t & 31, w = t >> 5;

    int c = g_counts[r];   // padded rows are 0 (never histogrammed)
    int incl = c;
    #pragma unroll
    for (int d = 1; d < 32; d <<= 1) {
        int n = __shfl_up_sync(0xffffffffu, incl, d);
        if (lane >= d) incl += n;
    }
    if (lane == 31) wsum[w] = incl;
    __syncthreads();
    if (t == 0) {
        int s = 0;
        #pragma unroll
        for (int i = 0; i < 8; i++) { int v = wsum[i]; wsum[i] = s; s += v; }
        sbase = atomicAdd(&g_base, s);
    }
    __syncthreads();

    int excl = (incl - c) + wsum[w] + sbase;
    g_offsets[r] = excl;
    g_cursor[r]  = excl;
}

// ---------------------------------------------------------------------------
// D: fill CSR edge array (2 edges/thread, independent atomics for MLP).
// ---------------------------------------------------------------------------
__global__ void fill_kernel(const int* __restrict__ ei,
                            const float* __restrict__ ew) {
    int i = blockIdx.x * blockDim.x + threadIdx.x;   // over N_EDGES/2
    if (i >= N_EDGES / 2) return;
    int2   rr = ((const int2*)ei)[i];
    int2   cc = ((const int2*)(ei + N_EDGES))[i];
    float2 ww = ((const float2*)ew)[i];
    int p0 = atomicAdd(&g_cursor[rr.x], 1);
    int p1 = atomicAdd(&g_cursor[rr.y], 1);
    g_edges[p0] = make_int2(cc.x, __float_as_int(ww.x));
    g_edges[p1] = make_int2(cc.y, __float_as_int(ww.y));
}

// ---------------------------------------------------------------------------
// E: support = X @ W  (128x128 block tile, 8x8 per thread).
// ---------------------------------------------------------------------------
#define TILE_M 128
#define LDS_PAD 132
#define GEMM_SMEM_BYTES (2 * TILE_M * LDS_PAD * 4)

__global__ __launch_bounds__(256, 1)
void gemm_kernel(const float* __restrict__ X,
                 const float* __restrict__ W,
                 float* __restrict__ sup) {
    extern __shared__ float smem[];
    float* Xs = smem;
    float* Wt = smem + TILE_M * LDS_PAD;

    const int tid  = threadIdx.x;
    const int row0 = blockIdx.x * TILE_M;

    for (int idx = tid; idx < TILE_M * (D / 4); idx += 256) {
        int r  = idx >> 5;
        int c4 = idx & 31;
        float4 v = make_float4(0.f, 0.f, 0.f, 0.f);
        int gr = row0 + r;
        if (gr < N_NODES)
            v = *(const float4*)(X + (size_t)gr * D + c4 * 4);
        float* dst = Xs + r * LDS_PAD + c4 * 4;
        dst[0] = v.x; dst[1] = v.y; dst[2] = v.z; dst[3] = v.w;
    }
    for (int idx = tid; idx < D * (D / 4); idx += 256) {
        int k  = idx >> 5;
        int c4 = idx & 31;
        float4 v = *(const float4*)(W + k * D + c4 * 4);
        Wt[(c4 * 4 + 0) * LDS_PAD + k] = v.x;
        Wt[(c4 * 4 + 1) * LDS_PAD + k] = v.y;
        Wt[(c4 * 4 + 2) * LDS_PAD + k] = v.z;
        Wt[(c4 * 4 + 3) * LDS_PAD + k] = v.w;
    }
    __syncthreads();

    const int ty = tid >> 4;
    const int tx = tid & 15;

    float acc[8][8];
    #pragma unroll
    for (int i = 0; i < 8; i++)
        #pragma unroll
        for (int j = 0; j < 8; j++)
            acc[i][j] = 0.f;

    #pragma unroll 2
    for (int k = 0; k < D; k += 4) {
        float4 xa[8], wb[8];
        #pragma unroll
        for (int i = 0; i < 8; i++)
            xa[i] = *(const float4*)(Xs + (ty + 16 * i) * LDS_PAD + k);
        #pragma unroll
        for (int j = 0; j < 8; j++)
            wb[j] = *(const float4*)(Wt + (tx + 16 * j) * LDS_PAD + k);
        #pragma unroll
        for (int i = 0; i < 8; i++) {
            #pragma unroll
            for (int j = 0; j < 8; j++) {
                acc[i][j] += xa[i].x * wb[j].x;
                acc[i][j] += xa[i].y * wb[j].y;
                acc[i][j] += xa[i].z * wb[j].z;
                acc[i][j] += xa[i].w * wb[j].w;
            }
        }
    }

    #pragma unroll
    for (int i = 0; i < 8; i++) {
        int gr = row0 + ty + 16 * i;
        if (gr < N_NODES) {
            #pragma unroll
            for (int j = 0; j < 8; j++)
                sup[(size_t)gr * D + tx + 16 * j] = acc[i][j];
        }
    }
}

// ---------------------------------------------------------------------------
// F: gather-aggregate v2. Block = 32 rows, 8 warps (4 rows/warp, lane l owns
// cols [4l,4l+4)). The block's CSR edge records are staged into smem with ONE
// coalesced pass; the gather loop reads metadata via LDS broadcast, killing
// the L2->L2 dependent chain. Unroll-4 gathers for MLP.
// ---------------------------------------------------------------------------
__global__ __launch_bounds__(256)
void gather_kernel(const float* __restrict__ sup,
                   const float* __restrict__ bias,
                   float* __restrict__ out) {
    __shared__ int2 recs[CHUNK];
    __shared__ int  sbeg[ROWS_PER_BLK], scnt[ROWS_PER_BLK];

    const int row0 = blockIdx.x * ROWS_PER_BLK;
    const int tid  = threadIdx.x;
    const int lane = tid & 31;
    const int w    = tid >> 5;

    if (tid < ROWS_PER_BLK) {
        sbeg[tid] = g_offsets[row0 + tid];
        scnt[tid] = g_counts[row0 + tid];
    }
    __syncthreads();

    const int blockBeg = sbeg[0];
    const int blockEnd = sbeg[ROWS_PER_BLK - 1] + scnt[ROWS_PER_BLK - 1];

    int rbeg[4], rend[4];
    float4 acc[4];
    #pragma unroll
    for (int i = 0; i < 4; i++) {
        rbeg[i] = sbeg[w * 4 + i];
        rend[i] = rbeg[i] + scnt[w * 4 + i];
        acc[i]  = make_float4(0.f, 0.f, 0.f, 0.f);
    }

    for (int cb = blockBeg; cb < blockEnd; cb += CHUNK) {
        const int n = min(CHUNK, blockEnd - cb);
        __syncthreads();
        for (int j = tid; j < n; j += 256)
            recs[j] = g_edges[cb + j];
        __syncthreads();

        #pragma unroll
        for (int i = 0; i < 4; i++) {
            int lo = max(rbeg[i], cb) - cb;
            int hi = min(rend[i], cb + n) - cb;
            int e  = lo;
            for (; e + 4 <= hi; e += 4) {
                int2 m0 = recs[e + 0], m1 = recs[e + 1];
                int2 m2 = recs[e + 2], m3 = recs[e + 3];
                float4 v0 = *(const float4*)(sup + (size_t)m0.x * D + lane * 4);
                float4 v1 = *(const float4*)(sup + (size_t)m1.x * D + lane * 4);
                float4 v2 = *(const float4*)(sup + (size_t)m2.x * D + lane * 4);
                float4 v3 = *(const float4*)(sup + (size_t)m3.x * D + lane * 4);
                float w0 = __int_as_float(m0.y), w1 = __int_as_float(m1.y);
                float w2 = __int_as_float(m2.y), w3 = __int_as_float(m3.y);
                acc[i].x += v0.x * w0; acc[i].y += v0.y * w0; acc[i].z += v0.z * w0; acc[i].w += v0.w * w0;
                acc[i].x += v1.x * w1; acc[i].y += v1.y * w1; acc[i].z += v1.z * w1; acc[i].w += v1.w * w1;
                acc[i].x += v2.x * w2; acc[i].y += v2.y * w2; acc[i].z += v2.z * w2; acc[i].w += v2.w * w2;
                acc[i].x += v3.x * w3; acc[i].y += v3.y * w3; acc[i].z += v3.z * w3; acc[i].w += v3.w * w3;
            }
            for (; e < hi; e++) {
                int2 m = recs[e];
                float4 v = *(const float4*)(sup + (size_t)m.x * D + lane * 4);
                float ww = __int_as_float(m.y);
                acc[i].x += v.x * ww; acc[i].y += v.y * ww;
                acc[i].z += v.z * ww; acc[i].w += v.w * ww;
            }
        }
    }

    float4 b = *(const float4*)(bias + lane * 4);
    #pragma unroll
    for (int i = 0; i < 4; i++) {
        int r = row0 + w * 4 + i;
        if (r < N_NODES) {
            float4 o = make_float4(acc[i].x + b.x, acc[i].y + b.y,
                                   acc[i].z + b.z, acc[i].w + b.w);
            *(float4*)(out + (size_t)r * D + lane * 4) = o;
        }
    }
}

// ---------------------------------------------------------------------------
extern "C" void kernel_launch(void* const* d_in, const int* in_sizes, int n_in,
                              void* d_out, int out_size) {
    const float* X    = (const float*)d_in[0];
    const int*   ei   = (const int*)  d_in[1];
    const float* ew   = (const float*)d_in[2];
    const float* W    = (const float*)d_in[3];
    const float* bias = (const float*)d_in[4];
    float* out = (float*)d_out;

    float* sup;
    cudaGetSymbolAddress((void**)&sup, g_support);

    cudaFuncSetAttribute(gemm_kernel, cudaFuncAttributeMaxDynamicSharedMemorySize,
                         GEMM_SMEM_BYTES);

    // CSR build
    zero_kernel<<<(ROWS_PAD + 255) / 256, 256>>>();
    hist_kernel<<<(N_EDGES / 4 + 255) / 256, 256>>>(ei);
    scan_kernel<<<ROWS_PAD / 256, 256>>>();
    fill_kernel<<<(N_EDGES / 2 + 255) / 256, 256>>>(ei, ew);

    // support = X @ W
    gemm_kernel<<<(N_NODES + TILE_M - 1) / TILE_M, 256, GEMM_SMEM_BYTES>>>(X, W, sup);

    // out = A @ support + bias  (no atomics)
    gather_kernel<<<ROWS_PAD / ROWS_PER_BLK, 256>>>(sup, bias, out);
}

// round 5
// speedup vs baseline: 1.8696x; 1.1108x over previous
#include <cuda_runtime.h>
#include <cuda_bf16.h>
#include <cstdint>

#define N_NODES 50000
#define N_EDGES 800000
#define D 128
#define ROWS_PAD 50176            // 196 * 256
#define ROWS_PER_BLK 32
#define CHUNK 1024

// Scratch (device globals: no allocation APIs allowed).
__device__ float g_support[(size_t)N_NODES * D];  // X @ W (25.6 MB)
__device__ int   g_counts[ROWS_PAD];
__device__ int   g_offsets[ROWS_PAD];
__device__ int   g_cursor[ROWS_PAD];
__device__ int2  g_edges[N_EDGES];                // (col, weight_bits), CSR-binned
__device__ int   g_base;                          // segment allocator

// ---------------------------------------------------------------------------
// A: zero counters + allocator.
// ---------------------------------------------------------------------------
__global__ void zero_kernel() {
    int i = blockIdx.x * blockDim.x + threadIdx.x;
    if (i < ROWS_PAD) g_counts[i] = 0;
    if (i == 0) g_base = 0;
}

// ---------------------------------------------------------------------------
// B: histogram of destination rows (4 edges/thread, vectorized).
// ---------------------------------------------------------------------------
__global__ void hist_kernel(const int* __restrict__ ei) {
    int i = blockIdx.x * blockDim.x + threadIdx.x;   // over N_EDGES/4
    if (i < N_EDGES / 4) {
        int4 r = ((const int4*)ei)[i];
        atomicAdd(&g_counts[r.x], 1);
        atomicAdd(&g_counts[r.y], 1);
        atomicAdd(&g_counts[r.z], 1);
        atomicAdd(&g_counts[r.w], 1);
    }
}

// ---------------------------------------------------------------------------
// C: block-parallel exclusive scan; blocks grab their base from a global
// allocator (segment order across 256-row groups is irrelevant).
// ---------------------------------------------------------------------------
__global__ __launch_bounds__(256)
void scan_kernel() {
    __shared__ int wsum[8];
    __shared__ int sbase;
    const int t = threadIdx.x;
    const int r = blockIdx.x * 256 + t;
    const int lane = t & 31, w = t >> 5;

    int c = g_counts[r];
    int incl = c;
    #pragma unroll
    for (int d = 1; d < 32; d <<= 1) {
        int n = __shfl_up_sync(0xffffffffu, incl, d);
        if (lane >= d) incl += n;
    }
    if (lane == 31) wsum[w] = incl;
    __syncthreads();
    if (t == 0) {
        int s = 0;
        #pragma unroll
        for (int i = 0; i < 8; i++) { int v = wsum[i]; wsum[i] = s; s += v; }
        sbase = atomicAdd(&g_base, s);
    }
    __syncthreads();

    int excl = (incl - c) + wsum[w] + sbase;
    g_offsets[r] = excl;
    g_cursor[r]  = excl;
}

// ---------------------------------------------------------------------------
// D: fill CSR edge array (4 edges/thread, 4 independent atomics in flight).
// ---------------------------------------------------------------------------
__global__ void fill_kernel(const int* __restrict__ ei,
                            const float* __restrict__ ew) {
    int i = blockIdx.x * blockDim.x + threadIdx.x;   // over N_EDGES/4
    if (i >= N_EDGES / 4) return;
    int4   rr = ((const int4*)ei)[i];
    int4   cc = ((const int4*)(ei + N_EDGES))[i];
    float4 ww = ((const float4*)ew)[i];
    int p0 = atomicAdd(&g_cursor[rr.x], 1);
    int p1 = atomicAdd(&g_cursor[rr.y], 1);
    int p2 = atomicAdd(&g_cursor[rr.z], 1);
    int p3 = atomicAdd(&g_cursor[rr.w], 1);
    g_edges[p0] = make_int2(cc.x, __float_as_int(ww.x));
    g_edges[p1] = make_int2(cc.y, __float_as_int(ww.y));
    g_edges[p2] = make_int2(cc.z, __float_as_int(ww.z));
    g_edges[p3] = make_int2(cc.w, __float_as_int(ww.w));
}

// ---------------------------------------------------------------------------
// E: support = X @ W  (128x128 block tile, 8x8 per thread).
// ---------------------------------------------------------------------------
#define TILE_M 128
#define LDS_PAD 132
#define GEMM_SMEM_BYTES (2 * TILE_M * LDS_PAD * 4)

__global__ __launch_bounds__(256, 1)
void gemm_kernel(const float* __restrict__ X,
                 const float* __restrict__ W,
                 float* __restrict__ sup) {
    extern __shared__ float smem[];
    float* Xs = smem;
    float* Wt = smem + TILE_M * LDS_PAD;

    const int tid  = threadIdx.x;
    const int row0 = blockIdx.x * TILE_M;

    for (int idx = tid; idx < TILE_M * (D / 4); idx += 256) {
        int r  = idx >> 5;
        int c4 = idx & 31;
        float4 v = make_float4(0.f, 0.f, 0.f, 0.f);
        int gr = row0 + r;
        if (gr < N_NODES)
            v = *(const float4*)(X + (size_t)gr * D + c4 * 4);
        float* dst = Xs + r * LDS_PAD + c4 * 4;
        dst[0] = v.x; dst[1] = v.y; dst[2] = v.z; dst[3] = v.w;
    }
    for (int idx = tid; idx < D * (D / 4); idx += 256) {
        int k  = idx >> 5;
        int c4 = idx & 31;
        float4 v = *(const float4*)(W + k * D + c4 * 4);
        Wt[(c4 * 4 + 0) * LDS_PAD + k] = v.x;
        Wt[(c4 * 4 + 1) * LDS_PAD + k] = v.y;
        Wt[(c4 * 4 + 2) * LDS_PAD + k] = v.z;
        Wt[(c4 * 4 + 3) * LDS_PAD + k] = v.w;
    }
    __syncthreads();

    const int ty = tid >> 4;
    const int tx = tid & 15;

    float acc[8][8];
    #pragma unroll
    for (int i = 0; i < 8; i++)
        #pragma unroll
        for (int j = 0; j < 8; j++)
            acc[i][j] = 0.f;

    #pragma unroll 2
    for (int k = 0; k < D; k += 4) {
        float4 xa[8], wb[8];
        #pragma unroll
        for (int i = 0; i < 8; i++)
            xa[i] = *(const float4*)(Xs + (ty + 16 * i) * LDS_PAD + k);
        #pragma unroll
        for (int j = 0; j < 8; j++)
            wb[j] = *(const float4*)(Wt + (tx + 16 * j) * LDS_PAD + k);
        #pragma unroll
        for (int i = 0; i < 8; i++) {
            #pragma unroll
            for (int j = 0; j < 8; j++) {
                acc[i][j] += xa[i].x * wb[j].x;
                acc[i][j] += xa[i].y * wb[j].y;
                acc[i][j] += xa[i].z * wb[j].z;
                acc[i][j] += xa[i].w * wb[j].w;
            }
        }
    }

    #pragma unroll
    for (int i = 0; i < 8; i++) {
        int gr = row0 + ty + 16 * i;
        if (gr < N_NODES) {
            #pragma unroll
            for (int j = 0; j < 8; j++)
                sup[(size_t)gr * D + tx + 16 * j] = acc[i][j];
        }
    }
}

// ---------------------------------------------------------------------------
// F: gather-aggregate. Block = 32 rows, 8 warps (4 rows/warp, lane l owns
// cols [4l,4l+4)). Edge records staged coalesced into smem once.
// ---------------------------------------------------------------------------
__global__ __launch_bounds__(256)
void gather_kernel(const float* __restrict__ sup,
                   const float* __restrict__ bias,
                   float* __restrict__ out) {
    __shared__ int2 recs[CHUNK];
    __shared__ int  sbeg[ROWS_PER_BLK], scnt[ROWS_PER_BLK];

    const int row0 = blockIdx.x * ROWS_PER_BLK;
    const int tid  = threadIdx.x;
    const int lane = tid & 31;
    const int w    = tid >> 5;

    if (tid < ROWS_PER_BLK) {
        sbeg[tid] = g_offsets[row0 + tid];
        scnt[tid] = g_counts[row0 + tid];
    }
    __syncthreads();

    const int blockBeg = sbeg[0];
    const int blockEnd = sbeg[ROWS_PER_BLK - 1] + scnt[ROWS_PER_BLK - 1];

    int rbeg[4], rend[4];
    float4 acc[4];
    #pragma unroll
    for (int i = 0; i < 4; i++) {
        rbeg[i] = sbeg[w * 4 + i];
        rend[i] = rbeg[i] + scnt[w * 4 + i];
        acc[i]  = make_float4(0.f, 0.f, 0.f, 0.f);
    }

    for (int cb = blockBeg; cb < blockEnd; cb += CHUNK) {
        const int n = min(CHUNK, blockEnd - cb);
        __syncthreads();
        for (int j = tid; j < n; j += 256)
            recs[j] = g_edges[cb + j];
        __syncthreads();

        #pragma unroll
        for (int i = 0; i < 4; i++) {
            int lo = max(rbeg[i], cb) - cb;
            int hi = min(rend[i], cb + n) - cb;
            int e  = lo;
            for (; e + 4 <= hi; e += 4) {
                int2 m0 = recs[e + 0], m1 = recs[e + 1];
                int2 m2 = recs[e + 2], m3 = recs[e + 3];
                float4 v0 = *(const float4*)(sup + (size_t)m0.x * D + lane * 4);
                float4 v1 = *(const float4*)(sup + (size_t)m1.x * D + lane * 4);
                float4 v2 = *(const float4*)(sup + (size_t)m2.x * D + lane * 4);
                float4 v3 = *(const float4*)(sup + (size_t)m3.x * D + lane * 4);
                float w0 = __int_as_float(m0.y), w1 = __int_as_float(m1.y);
                float w2 = __int_as_float(m2.y), w3 = __int_as_float(m3.y);
                acc[i].x += v0.x * w0; acc[i].y += v0.y * w0; acc[i].z += v0.z * w0; acc[i].w += v0.w * w0;
                acc[i].x += v1.x * w1; acc[i].y += v1.y * w1; acc[i].z += v1.z * w1; acc[i].w += v1.w * w1;
                acc[i].x += v2.x * w2; acc[i].y += v2.y * w2; acc[i].z += v2.z * w2; acc[i].w += v2.w * w2;
                acc[i].x += v3.x * w3; acc[i].y += v3.y * w3; acc[i].z += v3.z * w3; acc[i].w += v3.w * w3;
            }
            for (; e < hi; e++) {
                int2 m = recs[e];
                float4 v = *(const float4*)(sup + (size_t)m.x * D + lane * 4);
                float ww = __int_as_float(m.y);
                acc[i].x += v.x * ww; acc[i].y += v.y * ww;
                acc[i].z += v.z * ww; acc[i].w += v.w * ww;
            }
        }
    }

    float4 b = *(const float4*)(bias + lane * 4);
    #pragma unroll
    for (int i = 0; i < 4; i++) {
        int r = row0 + w * 4 + i;
        if (r < N_NODES) {
            float4 o = make_float4(acc[i].x + b.x, acc[i].y + b.y,
                                   acc[i].z + b.z, acc[i].w + b.w);
            *(float4*)(out + (size_t)r * D + lane * 4) = o;
        }
    }
}

// ---------------------------------------------------------------------------
extern "C" void kernel_launch(void* const* d_in, const int* in_sizes, int n_in,
                              void* d_out, int out_size) {
    const float* X    = (const float*)d_in[0];
    const int*   ei   = (const int*)  d_in[1];
    const float* ew   = (const float*)d_in[2];
    const float* W    = (const float*)d_in[3];
    const float* bias = (const float*)d_in[4];
    float* out = (float*)d_out;

    float* sup;
    cudaGetSymbolAddress((void**)&sup, g_support);

    // Lazy host-object init (first call is the non-captured correctness run;
    // these are host/driver objects, not device memory).
    static cudaStream_t s2 = nullptr;
    static cudaEvent_t  e_fork = nullptr, e_join = nullptr;
    if (!s2) {
        cudaStreamCreateWithFlags(&s2, cudaStreamNonBlocking);
        cudaEventCreateWithFlags(&e_fork, cudaEventDisableTiming);
        cudaEventCreateWithFlags(&e_join, cudaEventDisableTiming);
        cudaFuncSetAttribute(gemm_kernel,
                             cudaFuncAttributeMaxDynamicSharedMemorySize,
                             GEMM_SMEM_BYTES);
    }

    // Fork: GEMM on side stream, concurrent with the CSR build.
    cudaEventRecord(e_fork, 0);
    cudaStreamWaitEvent(s2, e_fork, 0);
    gemm_kernel<<<(N_NODES + TILE_M - 1) / TILE_M, 256, GEMM_SMEM_BYTES, s2>>>(X, W, sup);
    cudaEventRecord(e_join, s2);

    // CSR build on the main (capture) stream.
    zero_kernel<<<(ROWS_PAD + 255) / 256, 256>>>();
    hist_kernel<<<(N_EDGES / 4 + 255) / 256, 256>>>(ei);
    scan_kernel<<<ROWS_PAD / 256, 256>>>();
    fill_kernel<<<(N_EDGES / 4 + 255) / 256, 256>>>(ei, ew);

    // Join: gather needs both gemm output and the CSR.
    cudaStreamWaitEvent(0, e_join, 0);
    gather_kernel<<<ROWS_PAD / ROWS_PER_BLK, 256>>>(sup, bias, out);
}